// round 7
// baseline (speedup 1.0000x reference)
#include <cuda_runtime.h>
#include <math.h>

#define BATCH   16
#define D_IN    1024
#define T_IN    4096
#define CB_SIZE 8192
#define CB_DIM  512
#define T1      2048
#define T2      1024

// Scratch — referenced only from device code.
__device__ float g_y1 [BATCH * CB_DIM * T1];    // 64 MB, conv1 out, [b][co][t]
__device__ float g_enc[BATCH * T2 * CB_DIM];    // 32 MB, conv2 out, [token][dim]
__device__ float g_cb [CB_SIZE * CB_DIM];       // 16 MB, normalized codebook [code][dim]

// ---------------- normalize codebook rows (natural layout) ----------------
__global__ void __launch_bounds__(128) cb_normalize_kernel(const float* __restrict__ cb) {
    __shared__ float ssum[128];
    int row = blockIdx.x;
    int tid = threadIdx.x;
    const float* r = cb + (size_t)row * CB_DIM;
    float s = 0.f;
    for (int i = tid; i < CB_DIM; i += 128) { float v = r[i]; s += v * v; }
    ssum[tid] = s;
    __syncthreads();
    for (int st = 64; st > 0; st >>= 1) {
        if (tid < st) ssum[tid] += ssum[tid + st];
        __syncthreads();
    }
    float inv = 1.f / fmaxf(sqrtf(ssum[0]), 1e-12f);
    for (int i = tid; i < CB_DIM; i += 128)
        g_cb[(size_t)row * CB_DIM + i] = r[i] * inv;
}

// ---------------- naive direct stride-2 conv1d (k=3, pad=1) ----------------
// One thread per output t; 4 output channels per block.
// STAGE 0: X = xin -> g_y1 ([b][co][t]).  STAGE 1: X = g_y1 -> g_enc ([tok][d]).
template <int CIN, int TIN, int STAGE>
__global__ void __launch_bounds__(128) conv_naive_kernel(const float* __restrict__ xin,
                                                         const float* __restrict__ W) {
    constexpr int TOUT = TIN / 2;
    const float* X = (STAGE == 0) ? xin : (const float*)g_y1;

    __shared__ float ws[4 * CIN * 3];

    int tid = threadIdx.x;
    int t   = blockIdx.x * 128 + tid;
    int co0 = blockIdx.y * 4;
    int b   = blockIdx.z;

    for (int i = tid; i < 4 * CIN * 3; i += 128)
        ws[i] = W[(size_t)co0 * CIN * 3 + i];
    __syncthreads();

    const float* Xb = X + (size_t)b * CIN * TIN;
    float a0 = 0.f, a1 = 0.f, a2 = 0.f, a3 = 0.f;

    #pragma unroll 4
    for (int ci = 0; ci < CIN; ci++) {
        const float* xr = Xb + (size_t)ci * TIN + 2 * t - 1;
        float x0 = 0.f;
        if (t > 0) x0 = xr[0];          // x[2t-1], only t==0 is OOB (zero pad)
        float x1 = xr[1];               // x[2t]
        float x2 = xr[2];               // x[2t+1] <= TIN-1 always
        const float* w = ws + ci * 3;
        a0 += w[0]               * x0 + w[1]               * x1 + w[2]               * x2;
        a1 += w[CIN * 3 + 0]     * x0 + w[CIN * 3 + 1]     * x1 + w[CIN * 3 + 2]     * x2;
        a2 += w[2 * CIN * 3 + 0] * x0 + w[2 * CIN * 3 + 1] * x1 + w[2 * CIN * 3 + 2] * x2;
        a3 += w[3 * CIN * 3 + 0] * x0 + w[3 * CIN * 3 + 1] * x1 + w[3 * CIN * 3 + 2] * x2;
    }

    if (STAGE == 0) {
        g_y1[((size_t)b * 512 + co0 + 0) * TOUT + t] = a0;
        g_y1[((size_t)b * 512 + co0 + 1) * TOUT + t] = a1;
        g_y1[((size_t)b * 512 + co0 + 2) * TOUT + t] = a2;
        g_y1[((size_t)b * 512 + co0 + 3) * TOUT + t] = a3;
    } else {
        size_t tok = (size_t)b * TOUT + t;          // token-major for scoring
        g_enc[tok * CB_DIM + co0 + 0] = a0;
        g_enc[tok * CB_DIM + co0 + 1] = a1;
        g_enc[tok * CB_DIM + co0 + 2] = a2;
        g_enc[tok * CB_DIM + co0 + 3] = a3;
    }
}

// ---------------- scoring: warp-per-code dot products + argmax ----------------
// Output written as FLOAT values of the argmax indices (harness compares float32).
__global__ void __launch_bounds__(256) score_naive_kernel(float* __restrict__ out) {
    __shared__ float enc[4][CB_DIM];
    int tid  = threadIdx.x;
    int tok0 = blockIdx.x * 4;

    for (int i = tid; i < 4 * CB_DIM; i += 256)
        enc[i >> 9][i & 511] = g_enc[(size_t)tok0 * CB_DIM + i];
    __syncthreads();

    int warp = tid >> 5, lane = tid & 31;
    float best[4]; int bidx[4];
    #pragma unroll
    for (int j = 0; j < 4; j++) { best[j] = -3.4e38f; bidx[j] = 0; }

    for (int n = warp; n < CB_SIZE; n += 8) {
        const float* c = g_cb + (size_t)n * CB_DIM;
        float s0 = 0.f, s1 = 0.f, s2 = 0.f, s3 = 0.f;
        #pragma unroll
        for (int i = 0; i < CB_DIM / 32; i++) {
            int d = lane + 32 * i;
            float cv = c[d];
            s0 += cv * enc[0][d];
            s1 += cv * enc[1][d];
            s2 += cv * enc[2][d];
            s3 += cv * enc[3][d];
        }
        #pragma unroll
        for (int off = 16; off > 0; off >>= 1) {
            s0 += __shfl_xor_sync(0xffffffffu, s0, off);
            s1 += __shfl_xor_sync(0xffffffffu, s1, off);
            s2 += __shfl_xor_sync(0xffffffffu, s2, off);
            s3 += __shfl_xor_sync(0xffffffffu, s3, off);
        }
        // n strictly increases per warp -> strict '>' keeps first occurrence
        if (s0 > best[0]) { best[0] = s0; bidx[0] = n; }
        if (s1 > best[1]) { best[1] = s1; bidx[1] = n; }
        if (s2 > best[2]) { best[2] = s2; bidx[2] = n; }
        if (s3 > best[3]) { best[3] = s3; bidx[3] = n; }
    }

    __shared__ float bs[8][4];
    __shared__ int   bi[8][4];
    if (lane == 0) {
        #pragma unroll
        for (int j = 0; j < 4; j++) { bs[warp][j] = best[j]; bi[warp][j] = bidx[j]; }
    }
    __syncthreads();
    if (tid < 4) {
        float bb = -3.4e38f; int ii = 0x7fffffff;
        for (int w = 0; w < 8; w++) {
            float v = bs[w][tid]; int idx = bi[w][tid];
            if (v > bb || (v == bb && idx < ii)) { bb = v; ii = idx; }
        }
        out[tok0 + tid] = (float)ii;    // float-valued index, exact for < 2^24
    }
}

extern "C" void kernel_launch(void* const* d_in, const int* in_sizes, int n_in,
                              void* d_out, int out_size) {
    // Resolve inputs by element count; positional fallback (dict order).
    const float *x = 0, *w1 = 0, *w2 = 0, *cb = 0;
    for (int i = 0; i < n_in; i++) {
        switch (in_sizes[i]) {
            case BATCH * D_IN * T_IN:   x  = (const float*)d_in[i]; break;  // 67108864
            case CB_DIM * D_IN * 3:     w1 = (const float*)d_in[i]; break;  // 1572864
            case CB_DIM * CB_DIM * 3:   w2 = (const float*)d_in[i]; break;  // 786432
            case CB_SIZE * CB_DIM:      cb = (const float*)d_in[i]; break;  // 4194304
        }
    }
    if (!x || !w1 || !w2 || !cb) {
        x  = (const float*)d_in[0];
        w1 = (const float*)d_in[1];
        w2 = (const float*)d_in[2];
        cb = (const float*)d_in[3];
    }

    cb_normalize_kernel<<<CB_SIZE, 128>>>(cb);
    conv_naive_kernel<D_IN, T_IN, 0><<<dim3(T1 / 128, 512 / 4, BATCH), 128>>>(x, w1);
    conv_naive_kernel<CB_DIM, T1, 1><<<dim3(T2 / 128, 512 / 4, BATCH), 128>>>(nullptr, w2);
    score_naive_kernel<<<(BATCH * T2) / 4, 256>>>((float*)d_out);
}

// round 8
// speedup vs baseline: 2.3391x; 2.3391x over previous
#include <cuda_runtime.h>
#include <math.h>

#define BATCH   16
#define D_IN    1024
#define T_IN    4096
#define CB_SIZE 8192
#define CB_DIM  512
#define T1      2048
#define T2      1024
#define NTOK    (BATCH * T2)        // 16384
#define NSPLIT  8                   // code splits in score grid
#define NTILES  8                   // n-tiles of 128 codes per split
#define NSLOT   (NSPLIT * NTILES)   // 64 partial slots per token

// Scratch — referenced only from device code.
__device__ float g_y1 [BATCH * CB_DIM * T1];   // 64 MB conv1 out [b][co][t]
__device__ float g_y2 [BATCH * CB_DIM * T2];   // 32 MB conv2 out [b][co][t]
__device__ float g_cbT[CB_DIM * CB_SIZE];      // 16 MB normalized codebook [d][code]
__device__ float g_inorm[CB_SIZE];
__device__ float g_pv[(size_t)NTOK * NSLOT];   // 4 MB partial best values
__device__ int   g_pi[(size_t)NTOK * NSLOT];   // 4 MB partial best indices

// ---------------- codebook inverse norms ----------------
__global__ void __launch_bounds__(128) norm_kernel(const float* __restrict__ cb) {
    __shared__ float red[4];
    int row = blockIdx.x;
    const float* r = cb + (size_t)row * CB_DIM;
    float s = 0.f;
    for (int i = threadIdx.x; i < CB_DIM; i += 128) { float v = r[i]; s += v * v; }
    #pragma unroll
    for (int o = 16; o; o >>= 1) s += __shfl_down_sync(0xffffffffu, s, o);
    if ((threadIdx.x & 31) == 0) red[threadIdx.x >> 5] = s;
    __syncthreads();
    if (threadIdx.x == 0) {
        float t = red[0] + red[1] + red[2] + red[3];
        g_inorm[row] = 1.f / fmaxf(sqrtf(t), 1e-12f);
    }
}

// ---------------- normalize + transpose codebook -> g_cbT[d][code] ----------------
__global__ void __launch_bounds__(256) transpose_norm_kernel(const float* __restrict__ cb) {
    __shared__ float tile[32][33];
    int r0 = blockIdx.x * 32;   // code rows
    int d0 = blockIdx.y * 32;   // dims
    int tx = threadIdx.x;
    int ty = threadIdx.y;
    #pragma unroll
    for (int i = ty; i < 32; i += 8)
        tile[i][tx] = cb[(size_t)(r0 + i) * CB_DIM + d0 + tx] * g_inorm[r0 + i];
    __syncthreads();
    #pragma unroll
    for (int i = ty; i < 32; i += 8)
        g_cbT[(size_t)(d0 + i) * CB_SIZE + r0 + tx] = tile[tx][i];
}

// ---------------- stride-2 conv1d (k=3, pad=1) as implicit GEMM ----------------
// STAGE 0: X = xin -> g_y1.  STAGE 1: X = g_y1 -> g_y2.  Both [b][co][t].
template <int CIN, int TIN, int STAGE>
__global__ void __launch_bounds__(256) conv_s2_kernel(const float* __restrict__ xin,
                                                      const float* __restrict__ W) {
    constexpr int TOUT = TIN / 2;
    const float* X = (STAGE == 0) ? xin : (const float*)g_y1;
    float*       Y = (STAGE == 0) ? g_y1 : g_y2;

    __shared__ float Ws[64][49];    // [co][ci*3+k]
    __shared__ float Xs[16][132];   // [ci][p], p = 2*t_local + k

    int t0  = blockIdx.x * 64;
    int co0 = blockIdx.y * 64;
    int b   = blockIdx.z;
    int tid = threadIdx.x;
    int tx  = tid & 15;    // t
    int ty  = tid >> 4;    // co

    float acc[4][4] = {};
    const float* Xb = X + (size_t)b * CIN * TIN;

    for (int c0 = 0; c0 < CIN; c0 += 16) {
        #pragma unroll
        for (int s = 0; s < 12; s++) {
            int idx = tid + s * 256;
            int co  = idx / 48;
            int r   = idx % 48;
            Ws[co][r] = W[(size_t)(co0 + co) * (CIN * 3) + (size_t)c0 * 3 + r];
        }
        #pragma unroll
        for (int s = 0; s < 9; s++) {
            int idx = tid + s * 256;
            if (idx < 16 * 132) {
                int ci = idx / 132, p = idx % 132;
                int tin = 2 * t0 - 1 + p;
                float v = 0.f;
                if (p < 129 && tin >= 0 && tin < TIN)
                    v = Xb[(size_t)(c0 + ci) * TIN + tin];
                Xs[ci][p] = v;
            }
        }
        __syncthreads();
        #pragma unroll
        for (int ci = 0; ci < 16; ci++) {
            #pragma unroll
            for (int k = 0; k < 3; k++) {
                float a[4], x[4];
                #pragma unroll
                for (int ii = 0; ii < 4; ii++) a[ii] = Ws[ty * 4 + ii][ci * 3 + k];
                #pragma unroll
                for (int jj = 0; jj < 4; jj++) x[jj] = Xs[ci][2 * (tx + 16 * jj) + k];
                #pragma unroll
                for (int ii = 0; ii < 4; ii++)
                    #pragma unroll
                    for (int jj = 0; jj < 4; jj++)
                        acc[ii][jj] = fmaf(a[ii], x[jj], acc[ii][jj]);
            }
        }
        __syncthreads();
    }
    #pragma unroll
    for (int ii = 0; ii < 4; ii++)
        #pragma unroll
        for (int jj = 0; jj < 4; jj++)
            Y[((size_t)b * 512 + co0 + ty * 4 + ii) * TOUT + t0 + tx + 16 * jj] = acc[ii][jj];
}

// ---------------- scoring GEMM: 128 tok x 128 codes, 8x8 micro, fused argmax ----------------
__global__ void __launch_bounds__(256, 2) score_kernel() {
    __shared__ float Es[2][8][128];   // [buf][kk][token]
    __shared__ float Cs[2][8][128];   // [buf][kk][code]

    int split = blockIdx.x;           // 0..7
    int ttile = blockIdx.y;           // 0..127
    int b  = ttile >> 3;
    int t0 = (ttile & 7) * 128;
    int tid = threadIdx.x;
    int ty  = tid >> 4;               // token dir, 0..15
    int tx  = tid & 15;               // code dir, 0..15
    int lkk = tid >> 5;               // loader row 0..7
    int lm  = tid & 31;               // loader float4 col 0..31

    const float* Ybase = g_y2 + (size_t)b * CB_DIM * T2 + t0;

    for (int nt = 0; nt < NTILES; nt++) {
        int n0 = split * (NTILES * 128) + nt * 128;

        float acc[8][8];
        #pragma unroll
        for (int i = 0; i < 8; i++)
            #pragma unroll
            for (int j = 0; j < 8; j++) acc[i][j] = 0.f;

        // preload chunk 0
        *(float4*)&Es[0][lkk][lm * 4] =
            *(const float4*)(Ybase + (size_t)lkk * T2 + lm * 4);
        *(float4*)&Cs[0][lkk][lm * 4] =
            *(const float4*)(g_cbT + (size_t)lkk * CB_SIZE + n0 + lm * 4);
        __syncthreads();

        int buf = 0;
        for (int k0 = 0; k0 < CB_DIM; k0 += 8) {
            if (k0 + 8 < CB_DIM) {
                *(float4*)&Es[buf ^ 1][lkk][lm * 4] =
                    *(const float4*)(Ybase + (size_t)(k0 + 8 + lkk) * T2 + lm * 4);
                *(float4*)&Cs[buf ^ 1][lkk][lm * 4] =
                    *(const float4*)(g_cbT + (size_t)(k0 + 8 + lkk) * CB_SIZE + n0 + lm * 4);
            }
            #pragma unroll
            for (int kk = 0; kk < 8; kk++) {
                float4 a0 = *(const float4*)&Es[buf][kk][ty * 8];
                float4 a1 = *(const float4*)&Es[buf][kk][ty * 8 + 4];
                float4 b0 = *(const float4*)&Cs[buf][kk][tx * 8];
                float4 b1 = *(const float4*)&Cs[buf][kk][tx * 8 + 4];
                float av[8] = {a0.x, a0.y, a0.z, a0.w, a1.x, a1.y, a1.z, a1.w};
                float bv[8] = {b0.x, b0.y, b0.z, b0.w, b1.x, b1.y, b1.z, b1.w};
                #pragma unroll
                for (int i = 0; i < 8; i++)
                    #pragma unroll
                    for (int j = 0; j < 8; j++)
                        acc[i][j] = fmaf(av[i], bv[j], acc[i][j]);
            }
            __syncthreads();
            buf ^= 1;
        }

        // per-tile argmax: local over jj, then 16-lane butterfly over tx
        #pragma unroll
        for (int i = 0; i < 8; i++) {
            float bvv = -3.4e38f; int bii = 0x7fffffff;
            #pragma unroll
            for (int j = 0; j < 8; j++) {
                int n = n0 + tx * 8 + j;
                float v = acc[i][j];
                if (v > bvv) { bvv = v; bii = n; }   // j ascending: strict > keeps lowest
            }
            #pragma unroll
            for (int off = 8; off > 0; off >>= 1) {
                float ov = __shfl_xor_sync(0xffffffffu, bvv, off);
                int   oi = __shfl_xor_sync(0xffffffffu, bii, off);
                if (ov > bvv || (ov == bvv && oi < bii)) { bvv = ov; bii = oi; }
            }
            if (tx == 0) {
                int token = ttile * 128 + ty * 8 + i;
                int slot  = split * NTILES + nt;     // ascending n order
                g_pv[(size_t)token * NSLOT + slot] = bvv;
                g_pi[(size_t)token * NSLOT + slot] = bii;
            }
        }
        __syncthreads();   // protect Es/Cs before next tile's preload
    }
}

// ---------------- combine partials -> float index output ----------------
__global__ void __launch_bounds__(256) finalize_kernel(float* __restrict__ out) {
    int token = blockIdx.x * 256 + threadIdx.x;
    if (token >= NTOK) return;
    const float* pv = g_pv + (size_t)token * NSLOT;
    const int*   pi = g_pi + (size_t)token * NSLOT;
    float bv = -3.4e38f; int bi = 0x7fffffff;
    for (int s = 0; s < NSLOT; s++) {       // slots in ascending-n order
        float v = pv[s]; int idx = pi[s];
        if (v > bv || (v == bv && idx < bi)) { bv = v; bi = idx; }
    }
    out[token] = (float)bi;
}

extern "C" void kernel_launch(void* const* d_in, const int* in_sizes, int n_in,
                              void* d_out, int out_size) {
    const float *x = 0, *w1 = 0, *w2 = 0, *cb = 0;
    for (int i = 0; i < n_in; i++) {
        switch (in_sizes[i]) {
            case BATCH * D_IN * T_IN:   x  = (const float*)d_in[i]; break;
            case CB_DIM * D_IN * 3:     w1 = (const float*)d_in[i]; break;
            case CB_DIM * CB_DIM * 3:   w2 = (const float*)d_in[i]; break;
            case CB_SIZE * CB_DIM:      cb = (const float*)d_in[i]; break;
        }
    }
    if (!x || !w1 || !w2 || !cb) {
        x  = (const float*)d_in[0];
        w1 = (const float*)d_in[1];
        w2 = (const float*)d_in[2];
        cb = (const float*)d_in[3];
    }

    norm_kernel<<<CB_SIZE, 128>>>(cb);
    transpose_norm_kernel<<<dim3(CB_SIZE / 32, CB_DIM / 32), dim3(32, 8)>>>(cb);

    conv_s2_kernel<D_IN, T_IN, 0><<<dim3(T1 / 64, 8, BATCH), 256>>>(x, w1);
    conv_s2_kernel<CB_DIM, T1, 1><<<dim3(T2 / 64, 8, BATCH), 256>>>(nullptr, w2);

    score_kernel<<<dim3(NSPLIT, 128), 256>>>();
    finalize_kernel<<<(NTOK + 255) / 256, 256>>>((float*)d_out);
}

// round 9
// speedup vs baseline: 2.7090x; 1.1581x over previous
#include <cuda_runtime.h>
#include <math.h>

#define BATCH   16
#define D_IN    1024
#define T_IN    4096
#define CB_SIZE 8192
#define CB_DIM  512
#define T1      2048
#define T2      1024
#define NTOK    (BATCH * T2)
#define NSPLIT  8
#define NTILES  8
#define NSLOT   (NSPLIT * NTILES)

// Scratch — referenced only from device code.
__device__ float g_y1 [BATCH * CB_DIM * T1];   // 64 MB conv1 out [b][co][t]
__device__ float g_y2 [BATCH * CB_DIM * T2];   // 32 MB conv2 out [b][co][t]
__device__ float g_cbT[CB_DIM * CB_SIZE];      // 16 MB normalized codebook [d][code]
__device__ float g_inorm[CB_SIZE];
__device__ float g_pv[(size_t)NTOK * NSLOT];
__device__ int   g_pi[(size_t)NTOK * NSLOT];

// ---------------- codebook inverse norms ----------------
__global__ void __launch_bounds__(128) norm_kernel(const float* __restrict__ cb) {
    __shared__ float red[4];
    int row = blockIdx.x;
    const float* r = cb + (size_t)row * CB_DIM;
    float s = 0.f;
    for (int i = threadIdx.x; i < CB_DIM; i += 128) { float v = r[i]; s += v * v; }
    #pragma unroll
    for (int o = 16; o; o >>= 1) s += __shfl_down_sync(0xffffffffu, s, o);
    if ((threadIdx.x & 31) == 0) red[threadIdx.x >> 5] = s;
    __syncthreads();
    if (threadIdx.x == 0) {
        float t = red[0] + red[1] + red[2] + red[3];
        g_inorm[row] = 1.f / fmaxf(sqrtf(t), 1e-12f);
    }
}

// ---------------- normalize + transpose codebook -> g_cbT[d][code] ----------------
__global__ void __launch_bounds__(256) transpose_norm_kernel(const float* __restrict__ cb) {
    __shared__ float tile[32][33];
    int r0 = blockIdx.x * 32;
    int d0 = blockIdx.y * 32;
    int tx = threadIdx.x;
    int ty = threadIdx.y;
    #pragma unroll
    for (int i = ty; i < 32; i += 8)
        tile[i][tx] = cb[(size_t)(r0 + i) * CB_DIM + d0 + tx] * g_inorm[r0 + i];
    __syncthreads();
    #pragma unroll
    for (int i = ty; i < 32; i += 8)
        g_cbT[(size_t)(d0 + i) * CB_SIZE + r0 + tx] = tile[tx][i];
}

// ---------------- stride-2 conv1d (k=3, pad=1), 128x128 tile, 8x8 micro ----------------
// Phase-split X smem: Xe[p]=x[2(t0+p)], Xo[q]=x[2(t0+q)-1].
// k=0 -> Xo[t], k=1 -> Xe[t], k=2 -> Xo[t+1]  (all unit-stride in t).
// Weights transposed in smem: Wt[ci*3+k][co] (float4 co-fragments).
template <int CIN, int TIN, int STAGE>
__global__ void __launch_bounds__(256, 2) conv_s2_kernel(const float* __restrict__ xin,
                                                         const float* __restrict__ W) {
    constexpr int TOUT = TIN / 2;
    const float* X = (STAGE == 0) ? xin : (const float*)g_y1;
    float*       Y = (STAGE == 0) ? g_y1 : g_y2;

    __shared__ float Wt[24][132];   // [ci*3+k][co], pad 128->132 (16B-mult row stride)
    __shared__ float Xe[8][128];    // even phase
    __shared__ float Xo[8][132];    // odd phase, 129 used

    int t0  = blockIdx.x * 128;
    int co0 = blockIdx.y * 128;
    int b   = blockIdx.z;
    int tid = threadIdx.x;
    int tx  = tid & 15;    // t dir
    int ty  = tid >> 4;    // co dir

    float acc[8][8];
    #pragma unroll
    for (int i = 0; i < 8; i++)
        #pragma unroll
        for (int j = 0; j < 8; j++) acc[i][j] = 0.f;

    const float* Xb = X + (size_t)b * CIN * TIN;

    for (int c0 = 0; c0 < CIN; c0 += 8) {
        // ---- load weights: 128 co x 24 = 768 float4-chunks of 4 -> 3 float4/thread
        #pragma unroll
        for (int s = 0; s < 3; s++) {
            int f  = tid + s * 256;        // 0..767
            int co = f / 6, q = f % 6;     // q: float4 index within 24-float row
            float4 w4 = *(const float4*)(W + (size_t)(co0 + co) * (CIN * 3) + c0 * 3 + q * 4);
            Wt[q * 4 + 0][co] = w4.x;
            Wt[q * 4 + 1][co] = w4.y;
            Wt[q * 4 + 2][co] = w4.z;
            Wt[q * 4 + 3][co] = w4.w;
        }
        // ---- load x[ci][2*t0 .. 2*t0+255] as float4, scatter even/odd phases
        #pragma unroll
        for (int s = 0; s < 2; s++) {
            int f  = tid + s * 256;        // 0..511
            int ci = f >> 6, u = f & 63;
            float4 x4 = *(const float4*)(Xb + (size_t)(c0 + ci) * TIN + 2 * t0 + u * 4);
            Xe[ci][2 * u]     = x4.x;      // x[2t0+4u]
            Xo[ci][2 * u + 1] = x4.y;      // x[2t0+4u+1] = x[2(t0+2u+1)-1]
            Xe[ci][2 * u + 1] = x4.z;      // x[2t0+4u+2]
            Xo[ci][2 * u + 2] = x4.w;      // x[2t0+4u+3] = x[2(t0+2u+2)-1]
        }
        if (tid < 8) {                      // Xo[ci][0] = x[2*t0-1], zero-pad at t0==0
            float v = 0.f;
            if (t0 > 0) v = Xb[(size_t)(c0 + tid) * TIN + 2 * t0 - 1];
            Xo[tid][0] = v;
        }
        __syncthreads();

        #pragma unroll
        for (int ci = 0; ci < 8; ci++) {
            float4 xe0 = *(const float4*)&Xe[ci][tx * 8];
            float4 xe1 = *(const float4*)&Xe[ci][tx * 8 + 4];
            float4 xo0 = *(const float4*)&Xo[ci][tx * 8];
            float4 xo1 = *(const float4*)&Xo[ci][tx * 8 + 4];
            float  xo8 = Xo[ci][tx * 8 + 8];
            float xm[8] = {xo0.x, xo0.y, xo0.z, xo0.w, xo1.x, xo1.y, xo1.z, xo1.w}; // x[2t-1]
            float xc[8] = {xe0.x, xe0.y, xe0.z, xe0.w, xe1.x, xe1.y, xe1.z, xe1.w}; // x[2t]
            float xp[8] = {xo0.y, xo0.z, xo0.w, xo1.x, xo1.y, xo1.z, xo1.w, xo8};   // x[2t+1]
            #pragma unroll
            for (int k = 0; k < 3; k++) {
                float4 a0 = *(const float4*)&Wt[ci * 3 + k][ty * 8];
                float4 a1 = *(const float4*)&Wt[ci * 3 + k][ty * 8 + 4];
                float av[8] = {a0.x, a0.y, a0.z, a0.w, a1.x, a1.y, a1.z, a1.w};
                const float* xv = (k == 0) ? xm : (k == 1) ? xc : xp;
                #pragma unroll
                for (int i = 0; i < 8; i++)
                    #pragma unroll
                    for (int j = 0; j < 8; j++)
                        acc[i][j] = fmaf(av[i], xv[j], acc[i][j]);
            }
        }
        __syncthreads();
    }

    #pragma unroll
    for (int i = 0; i < 8; i++) {
        float* yr = Y + ((size_t)b * 512 + co0 + ty * 8 + i) * TOUT + t0 + tx * 8;
        *(float4*)yr       = make_float4(acc[i][0], acc[i][1], acc[i][2], acc[i][3]);
        *(float4*)(yr + 4) = make_float4(acc[i][4], acc[i][5], acc[i][6], acc[i][7]);
    }
}

// ---------------- scoring GEMM: 128 tok x 128 codes, 8x8 micro, fused argmax ----------------
__global__ void __launch_bounds__(256, 2) score_kernel() {
    __shared__ float Es[2][8][128];
    __shared__ float Cs[2][8][128];

    int split = blockIdx.x;
    int ttile = blockIdx.y;
    int b  = ttile >> 3;
    int t0 = (ttile & 7) * 128;
    int tid = threadIdx.x;
    int ty  = tid >> 4;
    int tx  = tid & 15;
    int lkk = tid >> 5;
    int lm  = tid & 31;

    const float* Ybase = g_y2 + (size_t)b * CB_DIM * T2 + t0;

    for (int nt = 0; nt < NTILES; nt++) {
        int n0 = split * (NTILES * 128) + nt * 128;

        float acc[8][8];
        #pragma unroll
        for (int i = 0; i < 8; i++)
            #pragma unroll
            for (int j = 0; j < 8; j++) acc[i][j] = 0.f;

        *(float4*)&Es[0][lkk][lm * 4] =
            *(const float4*)(Ybase + (size_t)lkk * T2 + lm * 4);
        *(float4*)&Cs[0][lkk][lm * 4] =
            *(const float4*)(g_cbT + (size_t)lkk * CB_SIZE + n0 + lm * 4);
        __syncthreads();

        int buf = 0;
        for (int k0 = 0; k0 < CB_DIM; k0 += 8) {
            if (k0 + 8 < CB_DIM) {
                *(float4*)&Es[buf ^ 1][lkk][lm * 4] =
                    *(const float4*)(Ybase + (size_t)(k0 + 8 + lkk) * T2 + lm * 4);
                *(float4*)&Cs[buf ^ 1][lkk][lm * 4] =
                    *(const float4*)(g_cbT + (size_t)(k0 + 8 + lkk) * CB_SIZE + n0 + lm * 4);
            }
            #pragma unroll
            for (int kk = 0; kk < 8; kk++) {
                float4 a0 = *(const float4*)&Es[buf][kk][ty * 8];
                float4 a1 = *(const float4*)&Es[buf][kk][ty * 8 + 4];
                float4 b0 = *(const float4*)&Cs[buf][kk][tx * 8];
                float4 b1 = *(const float4*)&Cs[buf][kk][tx * 8 + 4];
                float av[8] = {a0.x, a0.y, a0.z, a0.w, a1.x, a1.y, a1.z, a1.w};
                float bv[8] = {b0.x, b0.y, b0.z, b0.w, b1.x, b1.y, b1.z, b1.w};
                #pragma unroll
                for (int i = 0; i < 8; i++)
                    #pragma unroll
                    for (int j = 0; j < 8; j++)
                        acc[i][j] = fmaf(av[i], bv[j], acc[i][j]);
            }
            __syncthreads();
            buf ^= 1;
        }

        #pragma unroll
        for (int i = 0; i < 8; i++) {
            float bvv = -3.4e38f; int bii = 0x7fffffff;
            #pragma unroll
            for (int j = 0; j < 8; j++) {
                int n = n0 + tx * 8 + j;
                float v = acc[i][j];
                if (v > bvv) { bvv = v; bii = n; }
            }
            #pragma unroll
            for (int off = 8; off > 0; off >>= 1) {
                float ov = __shfl_xor_sync(0xffffffffu, bvv, off);
                int   oi = __shfl_xor_sync(0xffffffffu, bii, off);
                if (ov > bvv || (ov == bvv && oi < bii)) { bvv = ov; bii = oi; }
            }
            if (tx == 0) {
                int token = ttile * 128 + ty * 8 + i;
                int slot  = split * NTILES + nt;
                g_pv[(size_t)token * NSLOT + slot] = bvv;
                g_pi[(size_t)token * NSLOT + slot] = bii;
            }
        }
        __syncthreads();
    }
}

// ---------------- combine partials -> float index output ----------------
__global__ void __launch_bounds__(256) finalize_kernel(float* __restrict__ out) {
    int token = blockIdx.x * 256 + threadIdx.x;
    if (token >= NTOK) return;
    const float* pv = g_pv + (size_t)token * NSLOT;
    const int*   pi = g_pi + (size_t)token * NSLOT;
    float bv = -3.4e38f; int bi = 0x7fffffff;
    for (int s = 0; s < NSLOT; s++) {
        float v = pv[s]; int idx = pi[s];
        if (v > bv || (v == bv && idx < bi)) { bv = v; bi = idx; }
    }
    out[token] = (float)bi;
}

extern "C" void kernel_launch(void* const* d_in, const int* in_sizes, int n_in,
                              void* d_out, int out_size) {
    const float *x = 0, *w1 = 0, *w2 = 0, *cb = 0;
    for (int i = 0; i < n_in; i++) {
        switch (in_sizes[i]) {
            case BATCH * D_IN * T_IN:   x  = (const float*)d_in[i]; break;
            case CB_DIM * D_IN * 3:     w1 = (const float*)d_in[i]; break;
            case CB_DIM * CB_DIM * 3:   w2 = (const float*)d_in[i]; break;
            case CB_SIZE * CB_DIM:      cb = (const float*)d_in[i]; break;
        }
    }
    if (!x || !w1 || !w2 || !cb) {
        x  = (const float*)d_in[0];
        w1 = (const float*)d_in[1];
        w2 = (const float*)d_in[2];
        cb = (const float*)d_in[3];
    }

    norm_kernel<<<CB_SIZE, 128>>>(cb);
    transpose_norm_kernel<<<dim3(CB_SIZE / 32, CB_DIM / 32), dim3(32, 8)>>>(cb);

    conv_s2_kernel<D_IN, T_IN, 0><<<dim3(T_IN / 256, 4, BATCH), 256>>>(x, w1);
    conv_s2_kernel<CB_DIM, T1, 1><<<dim3(T1 / 256, 4, BATCH), 256>>>(nullptr, w2);

    score_kernel<<<dim3(NSPLIT, 128), 256>>>();
    finalize_kernel<<<(NTOK + 255) / 256, 256>>>((float*)d_out);
}